// round 15
// baseline (speedup 1.0000x reference)
#include <cuda_runtime.h>
#include <cuda_fp16.h>

#define NN 50000
#define NE 800000
#define HID 64
#define HEADS 3
#define F3 192           // HEADS*HID
#define NCLS 8
#define FULLM 0xffffffffu

// ---------------- static device scratch (no allocations allowed) ----------------
__device__ __half g_feat[NN * F3];      // per-layer projected features, fp16 [N, 192] (19.2 MB, L2-resident)
__device__ float  g_h[NN * HID];        // per-layer node output (input to next layer), fp32
__device__ float4 g_el[NN];             // (el0, el1, el2, unused)
__device__ float4 g_er[NN];
__device__ int    g_deg[NN];
__device__ int    g_cur[NN];
__device__ int    g_off[NN + 1];
__device__ int    g_csr_src[NE];        // src node ids, grouped by dst

__device__ __forceinline__ float lrelu(float x, float s) { return x > 0.f ? x : x * s; }

// f32x2 packed FMA helpers (SASS FFMA2 — only reachable via PTX fma.rn.f32x2)
__device__ __forceinline__ unsigned long long dup2(float x) {
    unsigned long long r;
    unsigned u = __float_as_uint(x);
    asm("mov.b64 %0, {%1, %1};" : "=l"(r) : "r"(u));
    return r;
}
__device__ __forceinline__ void fma2(unsigned long long& d, unsigned long long a, unsigned long long b) {
    asm("fma.rn.f32x2 %0, %1, %2, %3;" : "=l"(d) : "l"(a), "l"(b), "l"(d));
}
__device__ __forceinline__ float f2lo(unsigned long long v) { return __uint_as_float((unsigned)(v & 0xffffffffULL)); }
__device__ __forceinline__ float f2hi(unsigned long long v) { return __uint_as_float((unsigned)(v >> 32)); }

// ---------------- CSR build ----------------
__global__ void zero_kernel() {
    int i = blockIdx.x * blockDim.x + threadIdx.x;
    if (i < NN) { g_deg[i] = 0; g_cur[i] = 0; }
}

__global__ void count_kernel(const int* __restrict__ dst) {
    int e = blockIdx.x * blockDim.x + threadIdx.x;
    if (e < NE) atomicAdd(&g_deg[dst[e]], 1);
}

__global__ void scan_kernel() {
    __shared__ int s[1024];
    int t = threadIdx.x;
    const int CH = (NN + 1023) / 1024;   // 49
    int lo = t * CH; if (lo > NN) lo = NN;
    int hi = lo + CH; if (hi > NN) hi = NN;
    int sum = 0;
    for (int i = lo; i < hi; i++) sum += g_deg[i];
    s[t] = sum;
    __syncthreads();
    for (int d = 1; d < 1024; d <<= 1) {
        int v = (t >= d) ? s[t - d] : 0;
        __syncthreads();
        s[t] += v;
        __syncthreads();
    }
    int run = (t == 0) ? 0 : s[t - 1];
    for (int i = lo; i < hi; i++) { g_off[i] = run; run += g_deg[i]; }
    if (t == 1023) g_off[NN] = s[1023];
}

__global__ void fill_kernel(const int* __restrict__ src, const int* __restrict__ dst) {
    int e = blockIdx.x * blockDim.x + threadIdx.x;
    if (e < NE) {
        int d = dst[e];
        int p = atomicAdd(&g_cur[d], 1);
        g_csr_src[g_off[d] + p] = src[e];
    }
}

// ---------------- projection GEMM + fused el/er: feat = h @ W  ([N,DIN] @ [DIN,192]) ----------------
// R14 version verbatim (best measured). 256 threads (8 warps), each warp computes 4 rows x 192 cols.
// Columns packed in pairs (c, c+96) into f32x2 accumulators -> FFMA2.
// Epilogue: el/er from fp32 accumulators; feat stored fp16.
template <int DIN>
__global__ void __launch_bounds__(256) gemm_kernel(const float* __restrict__ hin,
                                                   const float* __restrict__ W,
                                                   const float* __restrict__ al,
                                                   const float* __restrict__ ar) {
    __shared__ float2 Ws[64 * 96];      // 48 KB
    const int lane = threadIdx.x & 31;
    const int warp = threadIdx.x >> 5;
    const int rowBase = blockIdx.x * 32 + warp * 4;
    const float* hp = hin ? hin : (const float*)g_h;
    const unsigned long long* Wsu = (const unsigned long long*)Ws;

    unsigned long long acc[4][3];
#pragma unroll
    for (int r = 0; r < 4; r++)
#pragma unroll
        for (int j = 0; j < 3; j++) acc[r][j] = 0ULL;

    for (int kt = 0; kt < DIN; kt += 64) {
        __syncthreads();
        // stage: 64 rows x 24 float4-pairs; Ws[k*96+c] = (W[k][c], W[k][c+96])
        for (int idx = threadIdx.x; idx < 64 * 24; idx += 256) {
            int k = idx / 24, cq = idx % 24;
            const float4* row = (const float4*)(W + (kt + k) * F3);
            float4 a = row[cq];
            float4 b = row[cq + 24];
            float2* d = &Ws[k * 96 + cq * 4];
            d[0] = make_float2(a.x, b.x);
            d[1] = make_float2(a.y, b.y);
            d[2] = make_float2(a.z, b.z);
            d[3] = make_float2(a.w, b.w);
        }
        __syncthreads();

        float h0[4], h1[4];
#pragma unroll
        for (int r = 0; r < 4; r++) {
            int row = rowBase + r;
            bool ok = row < NN;
            h0[r] = ok ? hp[row * DIN + kt + lane]      : 0.f;
            h1[r] = ok ? hp[row * DIN + kt + 32 + lane] : 0.f;
        }
#pragma unroll 8
        for (int kk = 0; kk < 32; kk++) {
            unsigned long long w0 = Wsu[kk * 96 + lane];
            unsigned long long w1 = Wsu[kk * 96 + lane + 32];
            unsigned long long w2 = Wsu[kk * 96 + lane + 64];
#pragma unroll
            for (int r = 0; r < 4; r++) {
                unsigned long long h2 = dup2(__shfl_sync(FULLM, h0[r], kk));
                fma2(acc[r][0], h2, w0);
                fma2(acc[r][1], h2, w1);
                fma2(acc[r][2], h2, w2);
            }
        }
#pragma unroll 8
        for (int kk = 0; kk < 32; kk++) {
            unsigned long long w0 = Wsu[(kk + 32) * 96 + lane];
            unsigned long long w1 = Wsu[(kk + 32) * 96 + lane + 32];
            unsigned long long w2 = Wsu[(kk + 32) * 96 + lane + 64];
#pragma unroll
            for (int r = 0; r < 4; r++) {
                unsigned long long h2 = dup2(__shfl_sync(FULLM, h1[r], kk));
                fma2(acc[r][0], h2, w0);
                fma2(acc[r][1], h2, w1);
                fma2(acc[r][2], h2, w2);
            }
        }
    }

    // al/ar constants for this lane's 6 columns: c = lane+32j (lo) and lane+96+32j (hi)
    float alc[6], arc[6];
#pragma unroll
    for (int j = 0; j < 3; j++) {
        alc[j]     = al[lane + 32 * j];
        alc[j + 3] = al[lane + 96 + 32 * j];
        arc[j]     = ar[lane + 32 * j];
        arc[j + 3] = ar[lane + 96 + 32 * j];
    }

#pragma unroll
    for (int r = 0; r < 4; r++) {
        int row = rowBase + r;
        if (row >= NN) continue;

        float lo0 = f2lo(acc[r][0]), lo1 = f2lo(acc[r][1]), lo2 = f2lo(acc[r][2]);
        float hi0 = f2hi(acc[r][0]), hi1 = f2hi(acc[r][1]), hi2 = f2hi(acc[r][2]);

        // store feat as fp16
        __half* fr = g_feat + row * F3;
        fr[lane]       = __float2half(lo0);
        fr[lane + 32]  = __float2half(lo1);
        fr[lane + 64]  = __float2half(lo2);
        fr[lane + 96]  = __float2half(hi0);
        fr[lane + 128] = __float2half(hi1);
        fr[lane + 160] = __float2half(hi2);

        // el/er per-lane partials (fp32, same grouping + reduction tree as before)
        float pl0 = fmaf(lo0, alc[0], lo1 * alc[1]);   // head0: cols lane, lane+32
        float pl1 = fmaf(lo2, alc[2], hi0 * alc[3]);   // head1: cols lane+64, lane+96
        float pl2 = fmaf(hi1, alc[4], hi2 * alc[5]);   // head2: cols lane+128, lane+160
        float pr0 = fmaf(lo0, arc[0], lo1 * arc[1]);
        float pr1 = fmaf(lo2, arc[2], hi0 * arc[3]);
        float pr2 = fmaf(hi1, arc[4], hi2 * arc[5]);
#pragma unroll
        for (int d = 16; d >= 1; d >>= 1) {
            pl0 += __shfl_xor_sync(FULLM, pl0, d);
            pl1 += __shfl_xor_sync(FULLM, pl1, d);
            pl2 += __shfl_xor_sync(FULLM, pl2, d);
            pr0 += __shfl_xor_sync(FULLM, pr0, d);
            pr1 += __shfl_xor_sync(FULLM, pr1, d);
            pr2 += __shfl_xor_sync(FULLM, pr2, d);
        }
        if (lane == 0) {
            g_el[row] = make_float4(pl0, pl1, pl2, 0.f);
            g_er[row] = make_float4(pr0, pr1, pr2, 0.f);
        }
    }
}

// ---------------- fused edge-softmax + aggregation + bias + LeakyReLU + head-mean ----------------
// One warp per destination node. SINGLE edge pass, no per-edge scratch (R14 structure).
// LAST=true additionally fuses the final projection out = h @ Wo + bo (deletes final_kernel
// and the layer-5 g_h round trip): lanes 0..15 hold h[4l..4l+3] in registers at the end.
template <bool LAST>
__global__ void __launch_bounds__(256) agg_kernel(const float* __restrict__ b,
                                                  const float* __restrict__ Wo,
                                                  const float* __restrict__ bo,
                                                  float* __restrict__ out) {
    int gw = (blockIdx.x * blockDim.x + threadIdx.x) >> 5;
    int lane = threadIdx.x & 31;
    if (gw >= NN) return;
    const int n = gw;
    const int base = g_off[n];
    const int deg  = g_off[n + 1] - base;
    const float4 er4 = g_er[n];

    float sm0 = 0.f, sm1 = 0.f, sm2 = 0.f;
    float a1x = 0.f, a1y = 0.f, a1z = 0.f, a1w = 0.f;
    float a2x = 0.f, a2y = 0.f, a2z = 0.f, a2w = 0.f;

    for (int i0 = 0; i0 < deg; i0 += 32) {
        int rem = deg - i0;
        int cnt = rem < 32 ? rem : 32;
        bool v = lane < cnt;
        int sL = v ? g_csr_src[base + i0 + lane] : 0;              // coalesced, parallel
        float ex0L = 0.f, ex1L = 0.f, ex2L = 0.f;
        if (v) {
            float4 el4 = g_el[sL];                                 // lane-parallel gather
            ex0L = __expf(lrelu(el4.x + er4.x, 0.2f));
            ex1L = __expf(lrelu(el4.y + er4.y, 0.2f));
            ex2L = __expf(lrelu(el4.z + er4.z, 0.2f));
            sm0 += ex0L; sm1 += ex1L; sm2 += ex2L;
        }

        int j = 0;
        for (; j + 4 <= cnt; j += 4) {
            uint2 v1[4], v2[4];
            float ah[4], ez[4];
#pragma unroll
            for (int q = 0; q < 4; q++) {
                int   s   = __shfl_sync(FULLM, sL,   j + q);
                float ex0 = __shfl_sync(FULLM, ex0L, j + q);
                float ex1 = __shfl_sync(FULLM, ex1L, j + q);
                ez[q]     = __shfl_sync(FULLM, ex2L, j + q);
                ah[q] = (lane < 16) ? ex0 : ex1;
                const __half* fr = g_feat + s * F3;
                v1[q] = *(const uint2*)(fr + 4 * lane);
                if (lane < 16) v2[q] = *(const uint2*)(fr + 128 + 4 * lane);
            }
#pragma unroll
            for (int q = 0; q < 4; q++) {
                float2 p0 = __half22float2(*(const __half2*)&v1[q].x);
                float2 p1 = __half22float2(*(const __half2*)&v1[q].y);
                a1x = fmaf(ah[q], p0.x, a1x);
                a1y = fmaf(ah[q], p0.y, a1y);
                a1z = fmaf(ah[q], p1.x, a1z);
                a1w = fmaf(ah[q], p1.y, a1w);
                if (lane < 16) {
                    float2 q0 = __half22float2(*(const __half2*)&v2[q].x);
                    float2 q1 = __half22float2(*(const __half2*)&v2[q].y);
                    a2x = fmaf(ez[q], q0.x, a2x);
                    a2y = fmaf(ez[q], q0.y, a2y);
                    a2z = fmaf(ez[q], q1.x, a2z);
                    a2w = fmaf(ez[q], q1.y, a2w);
                }
            }
        }
        for (; j < cnt; j++) {
            int   s   = __shfl_sync(FULLM, sL,   j);
            float ex0 = __shfl_sync(FULLM, ex0L, j);
            float ex1 = __shfl_sync(FULLM, ex1L, j);
            float ex2 = __shfl_sync(FULLM, ex2L, j);
            float ah = (lane < 16) ? ex0 : ex1;
            const __half* fr = g_feat + s * F3;
            uint2 v1 = *(const uint2*)(fr + 4 * lane);
            float2 p0 = __half22float2(*(const __half2*)&v1.x);
            float2 p1 = __half22float2(*(const __half2*)&v1.y);
            a1x = fmaf(ah, p0.x, a1x);
            a1y = fmaf(ah, p0.y, a1y);
            a1z = fmaf(ah, p1.x, a1z);
            a1w = fmaf(ah, p1.y, a1w);
            if (lane < 16) {
                uint2 v2 = *(const uint2*)(fr + 128 + 4 * lane);
                float2 q0 = __half22float2(*(const __half2*)&v2.x);
                float2 q1 = __half22float2(*(const __half2*)&v2.y);
                a2x = fmaf(ex2, q0.x, a2x);
                a2y = fmaf(ex2, q0.y, a2y);
                a2z = fmaf(ex2, q1.x, a2z);
                a2w = fmaf(ex2, q1.y, a2w);
            }
        }
    }

    // reduce softmax sums across lanes
#pragma unroll
    for (int d = 16; d >= 1; d >>= 1) {
        sm0 += __shfl_xor_sync(FULLM, sm0, d);
        sm1 += __shfl_xor_sync(FULLM, sm1, d);
        sm2 += __shfl_xor_sync(FULLM, sm2, d);
    }
    float inv0 = sm0 > 0.f ? 1.f / sm0 : 0.f;
    float inv1 = sm1 > 0.f ? 1.f / sm1 : 0.f;
    float inv2 = sm2 > 0.f ? 1.f / sm2 : 0.f;

    // normalize (per-lane head inverse), then gather head-1 accumulators into lanes 0..15
    float invA = (lane < 16) ? inv0 : inv1;
    a1x *= invA; a1y *= invA; a1z *= invA; a1w *= invA;
    a2x *= inv2; a2y *= inv2; a2z *= inv2; a2w *= inv2;

    float h1x = __shfl_down_sync(FULLM, a1x, 16);
    float h1y = __shfl_down_sync(FULLM, a1y, 16);
    float h1z = __shfl_down_sync(FULLM, a1z, 16);
    float h1w = __shfl_down_sync(FULLM, a1w, 16);

    // lanes 0..15 compute o = h[4*lane .. 4*lane+3]
    float4 o = make_float4(0.f, 0.f, 0.f, 0.f);
    if (lane < 16) {
        const float4* bb = (const float4*)b;
        float4 B0 = bb[lane], B1 = bb[16 + lane], B2 = bb[32 + lane];
        const float third = 1.f / 3.f;
        o.x = (lrelu(a1x + B0.x, 0.01f) + lrelu(h1x + B1.x, 0.01f) + lrelu(a2x + B2.x, 0.01f)) * third;
        o.y = (lrelu(a1y + B0.y, 0.01f) + lrelu(h1y + B1.y, 0.01f) + lrelu(a2y + B2.y, 0.01f)) * third;
        o.z = (lrelu(a1z + B0.z, 0.01f) + lrelu(h1z + B1.z, 0.01f) + lrelu(a2z + B2.z, 0.01f)) * third;
        o.w = (lrelu(a1w + B0.w, 0.01f) + lrelu(h1w + B1.w, 0.01f) + lrelu(a2w + B2.w, 0.01f)) * third;
        if (!LAST) ((float4*)(g_h + n * HID))[lane] = o;
    }

    if (LAST) {
        // fused final projection: out[n] = h @ Wo + bo   (h held across lanes 0..15, 4 vals each)
        float p[8];
#pragma unroll
        for (int c = 0; c < 8; c++) p[c] = 0.f;
        if (lane < 16) {
            const float4* wr = (const float4*)(Wo + (4 * lane) * 8);  // rows 4l..4l+3, 2 float4 each
            float hv[4] = {o.x, o.y, o.z, o.w};
#pragma unroll
            for (int j = 0; j < 4; j++) {
                float4 wa = wr[2 * j];
                float4 wb = wr[2 * j + 1];
                p[0] = fmaf(hv[j], wa.x, p[0]);
                p[1] = fmaf(hv[j], wa.y, p[1]);
                p[2] = fmaf(hv[j], wa.z, p[2]);
                p[3] = fmaf(hv[j], wa.w, p[3]);
                p[4] = fmaf(hv[j], wb.x, p[4]);
                p[5] = fmaf(hv[j], wb.y, p[5]);
                p[6] = fmaf(hv[j], wb.z, p[6]);
                p[7] = fmaf(hv[j], wb.w, p[7]);
            }
        }
#pragma unroll
        for (int d = 8; d >= 1; d >>= 1) {
#pragma unroll
            for (int c = 0; c < 8; c++) p[c] += __shfl_xor_sync(FULLM, p[c], d);
        }
        if (lane == 0) {
            float4 o0 = make_float4(p[0] + bo[0], p[1] + bo[1], p[2] + bo[2], p[3] + bo[3]);
            float4 o1 = make_float4(p[4] + bo[4], p[5] + bo[5], p[6] + bo[6], p[7] + bo[7]);
            ((float4*)(out + n * 8))[0] = o0;
            ((float4*)(out + n * 8))[1] = o1;
        }
    }
}

// ---------------- launch ----------------
extern "C" void kernel_launch(void* const* d_in, const int* in_sizes, int n_in,
                              void* d_out, int out_size) {
    const float* x   = (const float*)d_in[0];
    const int*   src = (const int*)d_in[1];
    const int*   dst = (const int*)d_in[2];
    const float* W[5], *b[5], *al[5], *ar[5];
    for (int l = 0; l < 5; l++) {
        int i = 3 + 4 * l;
        W[l]  = (const float*)d_in[i];
        b[l]  = (const float*)d_in[i + 1];
        al[l] = (const float*)d_in[i + 2];
        ar[l] = (const float*)d_in[i + 3];
    }
    const float* Wo = (const float*)d_in[23];
    const float* bo = (const float*)d_in[24];
    float* out = (float*)d_out;

    const int NB_N = (NN + 255) / 256;
    const int NB_E = (NE + 255) / 256;
    const int NB_W = (NN * 32 + 255) / 256;   // warp-per-node kernels
    const int NB_G = (NN + 31) / 32;          // gemm: 32 rows/block

    // Launch order puts gemm1 in the ncu capture slot (4th launch, where fill_kernel was
    // captured in prior rounds). gemm1 has no CSR dependency, so this reorder is legal:
    // fill needs scan/count/zero; agg1 needs fill + gemm1. Stream is in-order.
    zero_kernel<<<NB_N, 256>>>();
    count_kernel<<<NB_E, 256>>>(dst);
    scan_kernel<<<1, 1024>>>();
    gemm_kernel<128><<<NB_G, 256>>>(x, W[0], al[0], ar[0]);     // <- profiled slot
    fill_kernel<<<NB_E, 256>>>(src, dst);
    agg_kernel<false><<<NB_W, 256>>>(b[0], nullptr, nullptr, nullptr);

    for (int l = 1; l < 5; l++) {
        gemm_kernel<64><<<NB_G, 256>>>(nullptr, W[l], al[l], ar[l]);  // nullptr -> read g_h
        if (l < 4) agg_kernel<false><<<NB_W, 256>>>(b[l], nullptr, nullptr, nullptr);
        else       agg_kernel<true><<<NB_W, 256>>>(b[l], Wo, bo, out);  // fused final projection
    }
}

// round 16
// speedup vs baseline: 1.0185x; 1.0185x over previous
#include <cuda_runtime.h>
#include <cuda_fp16.h>

#define NN 50000
#define NE 800000
#define HID 64
#define HEADS 3
#define F3 192           // HEADS*HID
#define NCLS 8
#define FULLM 0xffffffffu

// ---------------- static device scratch (no allocations allowed) ----------------
__device__ __half g_feat[NN * F3];      // per-layer projected features, fp16 [N, 192] (19.2 MB, L2-resident)
__device__ float  g_h[NN * HID];        // per-layer node output (input to next layer), fp32
__device__ float4 g_el[NN];             // (el0, el1, el2, unused)
__device__ float4 g_er[NN];
__device__ int    g_deg[NN];
__device__ int    g_cur[NN];
__device__ int    g_off[NN + 1];
__device__ int    g_csr_src[NE];        // src node ids, grouped by dst

__device__ __forceinline__ float lrelu(float x, float s) { return x > 0.f ? x : x * s; }

// f32x2 packed FMA helpers (SASS FFMA2 — only reachable via PTX fma.rn.f32x2)
__device__ __forceinline__ unsigned long long dup2(float x) {
    unsigned long long r;
    unsigned u = __float_as_uint(x);
    asm("mov.b64 %0, {%1, %1};" : "=l"(r) : "r"(u));
    return r;
}
__device__ __forceinline__ void fma2(unsigned long long& d, unsigned long long a, unsigned long long b) {
    asm("fma.rn.f32x2 %0, %1, %2, %3;" : "=l"(d) : "l"(a), "l"(b), "l"(d));
}
__device__ __forceinline__ float f2lo(unsigned long long v) { return __uint_as_float((unsigned)(v & 0xffffffffULL)); }
__device__ __forceinline__ float f2hi(unsigned long long v) { return __uint_as_float((unsigned)(v >> 32)); }

// ---------------- CSR build ----------------
__global__ void zero_kernel() {
    int i = blockIdx.x * blockDim.x + threadIdx.x;
    if (i < NN) { g_deg[i] = 0; g_cur[i] = 0; }
}

__global__ void count_kernel(const int* __restrict__ dst) {
    int e = blockIdx.x * blockDim.x + threadIdx.x;
    if (e < NE) atomicAdd(&g_deg[dst[e]], 1);
}

__global__ void scan_kernel() {
    __shared__ int s[1024];
    int t = threadIdx.x;
    const int CH = (NN + 1023) / 1024;   // 49
    int lo = t * CH; if (lo > NN) lo = NN;
    int hi = lo + CH; if (hi > NN) hi = NN;
    int sum = 0;
    for (int i = lo; i < hi; i++) sum += g_deg[i];
    s[t] = sum;
    __syncthreads();
    for (int d = 1; d < 1024; d <<= 1) {
        int v = (t >= d) ? s[t - d] : 0;
        __syncthreads();
        s[t] += v;
        __syncthreads();
    }
    int run = (t == 0) ? 0 : s[t - 1];
    for (int i = lo; i < hi; i++) { g_off[i] = run; run += g_deg[i]; }
    if (t == 1023) g_off[NN] = s[1023];
}

__global__ void fill_kernel(const int* __restrict__ src, const int* __restrict__ dst) {
    int e = blockIdx.x * blockDim.x + threadIdx.x;
    if (e < NE) {
        int d = dst[e];
        int p = atomicAdd(&g_cur[d], 1);
        g_csr_src[g_off[d] + p] = src[e];
    }
}

// ---------------- projection GEMM + fused el/er: feat = h @ W  ([N,DIN] @ [DIN,192]) ----------------
// 256 threads (8 warps), each warp computes 8 rows x 192 cols (64 rows/block).
// Rationale (R15 ncu): L1TEX 85% vs FMA 38% — crossbar-bound. 8 rows/warp halves W-tile
// LDS bytes per FFMA2 (3 LDS.64 now feed 24 FFMA2), making the FMA pipe the binding resource.
// Columns packed in pairs (c, c+96) into f32x2 accumulators -> FFMA2.
// Epilogue: el/er from fp32 accumulators; feat stored fp16. Per-row math bit-identical to R15.
template <int DIN>
__global__ void __launch_bounds__(256) gemm_kernel(const float* __restrict__ hin,
                                                   const float* __restrict__ W,
                                                   const float* __restrict__ al,
                                                   const float* __restrict__ ar) {
    __shared__ float2 Ws[64 * 96];      // 48 KB
    const int lane = threadIdx.x & 31;
    const int warp = threadIdx.x >> 5;
    const int rowBase = blockIdx.x * 64 + warp * 8;
    const float* hp = hin ? hin : (const float*)g_h;
    const unsigned long long* Wsu = (const unsigned long long*)Ws;

    unsigned long long acc[8][3];
#pragma unroll
    for (int r = 0; r < 8; r++)
#pragma unroll
        for (int j = 0; j < 3; j++) acc[r][j] = 0ULL;

    for (int kt = 0; kt < DIN; kt += 64) {
        __syncthreads();
        // stage: 64 rows x 24 float4-pairs; Ws[k*96+c] = (W[k][c], W[k][c+96])
        for (int idx = threadIdx.x; idx < 64 * 24; idx += 256) {
            int k = idx / 24, cq = idx % 24;
            const float4* row = (const float4*)(W + (kt + k) * F3);
            float4 a = row[cq];
            float4 b = row[cq + 24];
            float2* d = &Ws[k * 96 + cq * 4];
            d[0] = make_float2(a.x, b.x);
            d[1] = make_float2(a.y, b.y);
            d[2] = make_float2(a.z, b.z);
            d[3] = make_float2(a.w, b.w);
        }
        __syncthreads();

        float h0[8], h1[8];
#pragma unroll
        for (int r = 0; r < 8; r++) {
            int row = rowBase + r;
            bool ok = row < NN;
            h0[r] = ok ? hp[row * DIN + kt + lane]      : 0.f;
            h1[r] = ok ? hp[row * DIN + kt + 32 + lane] : 0.f;
        }
#pragma unroll 4
        for (int kk = 0; kk < 32; kk++) {
            unsigned long long w0 = Wsu[kk * 96 + lane];
            unsigned long long w1 = Wsu[kk * 96 + lane + 32];
            unsigned long long w2 = Wsu[kk * 96 + lane + 64];
#pragma unroll
            for (int r = 0; r < 8; r++) {
                unsigned long long h2 = dup2(__shfl_sync(FULLM, h0[r], kk));
                fma2(acc[r][0], h2, w0);
                fma2(acc[r][1], h2, w1);
                fma2(acc[r][2], h2, w2);
            }
        }
#pragma unroll 4
        for (int kk = 0; kk < 32; kk++) {
            unsigned long long w0 = Wsu[(kk + 32) * 96 + lane];
            unsigned long long w1 = Wsu[(kk + 32) * 96 + lane + 32];
            unsigned long long w2 = Wsu[(kk + 32) * 96 + lane + 64];
#pragma unroll
            for (int r = 0; r < 8; r++) {
                unsigned long long h2 = dup2(__shfl_sync(FULLM, h1[r], kk));
                fma2(acc[r][0], h2, w0);
                fma2(acc[r][1], h2, w1);
                fma2(acc[r][2], h2, w2);
            }
        }
    }

    // al/ar constants for this lane's 6 columns: c = lane+32j (lo) and lane+96+32j (hi)
    float alc[6], arc[6];
#pragma unroll
    for (int j = 0; j < 3; j++) {
        alc[j]     = al[lane + 32 * j];
        alc[j + 3] = al[lane + 96 + 32 * j];
        arc[j]     = ar[lane + 32 * j];
        arc[j + 3] = ar[lane + 96 + 32 * j];
    }

#pragma unroll
    for (int r = 0; r < 8; r++) {
        int row = rowBase + r;
        if (row >= NN) continue;

        float lo0 = f2lo(acc[r][0]), lo1 = f2lo(acc[r][1]), lo2 = f2lo(acc[r][2]);
        float hi0 = f2hi(acc[r][0]), hi1 = f2hi(acc[r][1]), hi2 = f2hi(acc[r][2]);

        // store feat as fp16
        __half* fr = g_feat + row * F3;
        fr[lane]       = __float2half(lo0);
        fr[lane + 32]  = __float2half(lo1);
        fr[lane + 64]  = __float2half(lo2);
        fr[lane + 96]  = __float2half(hi0);
        fr[lane + 128] = __float2half(hi1);
        fr[lane + 160] = __float2half(hi2);

        // el/er per-lane partials (fp32, same grouping + reduction tree as before)
        float pl0 = fmaf(lo0, alc[0], lo1 * alc[1]);   // head0: cols lane, lane+32
        float pl1 = fmaf(lo2, alc[2], hi0 * alc[3]);   // head1: cols lane+64, lane+96
        float pl2 = fmaf(hi1, alc[4], hi2 * alc[5]);   // head2: cols lane+128, lane+160
        float pr0 = fmaf(lo0, arc[0], lo1 * arc[1]);
        float pr1 = fmaf(lo2, arc[2], hi0 * arc[3]);
        float pr2 = fmaf(hi1, arc[4], hi2 * arc[5]);
#pragma unroll
        for (int d = 16; d >= 1; d >>= 1) {
            pl0 += __shfl_xor_sync(FULLM, pl0, d);
            pl1 += __shfl_xor_sync(FULLM, pl1, d);
            pl2 += __shfl_xor_sync(FULLM, pl2, d);
            pr0 += __shfl_xor_sync(FULLM, pr0, d);
            pr1 += __shfl_xor_sync(FULLM, pr1, d);
            pr2 += __shfl_xor_sync(FULLM, pr2, d);
        }
        if (lane == 0) {
            g_el[row] = make_float4(pl0, pl1, pl2, 0.f);
            g_er[row] = make_float4(pr0, pr1, pr2, 0.f);
        }
    }
}

// ---------------- fused edge-softmax + aggregation + bias + LeakyReLU + head-mean ----------------
// One warp per destination node. SINGLE edge pass, no per-edge scratch (R14 structure).
// LAST=true additionally fuses the final projection out = h @ Wo + bo.
template <bool LAST>
__global__ void __launch_bounds__(256) agg_kernel(const float* __restrict__ b,
                                                  const float* __restrict__ Wo,
                                                  const float* __restrict__ bo,
                                                  float* __restrict__ out) {
    int gw = (blockIdx.x * blockDim.x + threadIdx.x) >> 5;
    int lane = threadIdx.x & 31;
    if (gw >= NN) return;
    const int n = gw;
    const int base = g_off[n];
    const int deg  = g_off[n + 1] - base;
    const float4 er4 = g_er[n];

    float sm0 = 0.f, sm1 = 0.f, sm2 = 0.f;
    float a1x = 0.f, a1y = 0.f, a1z = 0.f, a1w = 0.f;
    float a2x = 0.f, a2y = 0.f, a2z = 0.f, a2w = 0.f;

    for (int i0 = 0; i0 < deg; i0 += 32) {
        int rem = deg - i0;
        int cnt = rem < 32 ? rem : 32;
        bool v = lane < cnt;
        int sL = v ? g_csr_src[base + i0 + lane] : 0;              // coalesced, parallel
        float ex0L = 0.f, ex1L = 0.f, ex2L = 0.f;
        if (v) {
            float4 el4 = g_el[sL];                                 // lane-parallel gather
            ex0L = __expf(lrelu(el4.x + er4.x, 0.2f));
            ex1L = __expf(lrelu(el4.y + er4.y, 0.2f));
            ex2L = __expf(lrelu(el4.z + er4.z, 0.2f));
            sm0 += ex0L; sm1 += ex1L; sm2 += ex2L;
        }

        int j = 0;
        for (; j + 4 <= cnt; j += 4) {
            uint2 v1[4], v2[4];
            float ah[4], ez[4];
#pragma unroll
            for (int q = 0; q < 4; q++) {
                int   s   = __shfl_sync(FULLM, sL,   j + q);
                float ex0 = __shfl_sync(FULLM, ex0L, j + q);
                float ex1 = __shfl_sync(FULLM, ex1L, j + q);
                ez[q]     = __shfl_sync(FULLM, ex2L, j + q);
                ah[q] = (lane < 16) ? ex0 : ex1;
                const __half* fr = g_feat + s * F3;
                v1[q] = *(const uint2*)(fr + 4 * lane);
                if (lane < 16) v2[q] = *(const uint2*)(fr + 128 + 4 * lane);
            }
#pragma unroll
            for (int q = 0; q < 4; q++) {
                float2 p0 = __half22float2(*(const __half2*)&v1[q].x);
                float2 p1 = __half22float2(*(const __half2*)&v1[q].y);
                a1x = fmaf(ah[q], p0.x, a1x);
                a1y = fmaf(ah[q], p0.y, a1y);
                a1z = fmaf(ah[q], p1.x, a1z);
                a1w = fmaf(ah[q], p1.y, a1w);
                if (lane < 16) {
                    float2 q0 = __half22float2(*(const __half2*)&v2[q].x);
                    float2 q1 = __half22float2(*(const __half2*)&v2[q].y);
                    a2x = fmaf(ez[q], q0.x, a2x);
                    a2y = fmaf(ez[q], q0.y, a2y);
                    a2z = fmaf(ez[q], q1.x, a2z);
                    a2w = fmaf(ez[q], q1.y, a2w);
                }
            }
        }
        for (; j < cnt; j++) {
            int   s   = __shfl_sync(FULLM, sL,   j);
            float ex0 = __shfl_sync(FULLM, ex0L, j);
            float ex1 = __shfl_sync(FULLM, ex1L, j);
            float ex2 = __shfl_sync(FULLM, ex2L, j);
            float ah = (lane < 16) ? ex0 : ex1;
            const __half* fr = g_feat + s * F3;
            uint2 v1 = *(const uint2*)(fr + 4 * lane);
            float2 p0 = __half22float2(*(const __half2*)&v1.x);
            float2 p1 = __half22float2(*(const __half2*)&v1.y);
            a1x = fmaf(ah, p0.x, a1x);
            a1y = fmaf(ah, p0.y, a1y);
            a1z = fmaf(ah, p1.x, a1z);
            a1w = fmaf(ah, p1.y, a1w);
            if (lane < 16) {
                uint2 v2 = *(const uint2*)(fr + 128 + 4 * lane);
                float2 q0 = __half22float2(*(const __half2*)&v2.x);
                float2 q1 = __half22float2(*(const __half2*)&v2.y);
                a2x = fmaf(ex2, q0.x, a2x);
                a2y = fmaf(ex2, q0.y, a2y);
                a2z = fmaf(ex2, q1.x, a2z);
                a2w = fmaf(ex2, q1.y, a2w);
            }
        }
    }

    // reduce softmax sums across lanes
#pragma unroll
    for (int d = 16; d >= 1; d >>= 1) {
        sm0 += __shfl_xor_sync(FULLM, sm0, d);
        sm1 += __shfl_xor_sync(FULLM, sm1, d);
        sm2 += __shfl_xor_sync(FULLM, sm2, d);
    }
    float inv0 = sm0 > 0.f ? 1.f / sm0 : 0.f;
    float inv1 = sm1 > 0.f ? 1.f / sm1 : 0.f;
    float inv2 = sm2 > 0.f ? 1.f / sm2 : 0.f;

    // normalize (per-lane head inverse), then gather head-1 accumulators into lanes 0..15
    float invA = (lane < 16) ? inv0 : inv1;
    a1x *= invA; a1y *= invA; a1z *= invA; a1w *= invA;
    a2x *= inv2; a2y *= inv2; a2z *= inv2; a2w *= inv2;

    float h1x = __shfl_down_sync(FULLM, a1x, 16);
    float h1y = __shfl_down_sync(FULLM, a1y, 16);
    float h1z = __shfl_down_sync(FULLM, a1z, 16);
    float h1w = __shfl_down_sync(FULLM, a1w, 16);

    // lanes 0..15 compute o = h[4*lane .. 4*lane+3]
    float4 o = make_float4(0.f, 0.f, 0.f, 0.f);
    if (lane < 16) {
        const float4* bb = (const float4*)b;
        float4 B0 = bb[lane], B1 = bb[16 + lane], B2 = bb[32 + lane];
        const float third = 1.f / 3.f;
        o.x = (lrelu(a1x + B0.x, 0.01f) + lrelu(h1x + B1.x, 0.01f) + lrelu(a2x + B2.x, 0.01f)) * third;
        o.y = (lrelu(a1y + B0.y, 0.01f) + lrelu(h1y + B1.y, 0.01f) + lrelu(a2y + B2.y, 0.01f)) * third;
        o.z = (lrelu(a1z + B0.z, 0.01f) + lrelu(h1z + B1.z, 0.01f) + lrelu(a2z + B2.z, 0.01f)) * third;
        o.w = (lrelu(a1w + B0.w, 0.01f) + lrelu(h1w + B1.w, 0.01f) + lrelu(a2w + B2.w, 0.01f)) * third;
        if (!LAST) ((float4*)(g_h + n * HID))[lane] = o;
    }

    if (LAST) {
        // fused final projection: out[n] = h @ Wo + bo   (h held across lanes 0..15, 4 vals each)
        float p[8];
#pragma unroll
        for (int c = 0; c < 8; c++) p[c] = 0.f;
        if (lane < 16) {
            const float4* wr = (const float4*)(Wo + (4 * lane) * 8);  // rows 4l..4l+3, 2 float4 each
            float hv[4] = {o.x, o.y, o.z, o.w};
#pragma unroll
            for (int j = 0; j < 4; j++) {
                float4 wa = wr[2 * j];
                float4 wb = wr[2 * j + 1];
                p[0] = fmaf(hv[j], wa.x, p[0]);
                p[1] = fmaf(hv[j], wa.y, p[1]);
                p[2] = fmaf(hv[j], wa.z, p[2]);
                p[3] = fmaf(hv[j], wa.w, p[3]);
                p[4] = fmaf(hv[j], wb.x, p[4]);
                p[5] = fmaf(hv[j], wb.y, p[5]);
                p[6] = fmaf(hv[j], wb.z, p[6]);
                p[7] = fmaf(hv[j], wb.w, p[7]);
            }
        }
#pragma unroll
        for (int d = 8; d >= 1; d >>= 1) {
#pragma unroll
            for (int c = 0; c < 8; c++) p[c] += __shfl_xor_sync(FULLM, p[c], d);
        }
        if (lane == 0) {
            float4 o0 = make_float4(p[0] + bo[0], p[1] + bo[1], p[2] + bo[2], p[3] + bo[3]);
            float4 o1 = make_float4(p[4] + bo[4], p[5] + bo[5], p[6] + bo[6], p[7] + bo[7]);
            ((float4*)(out + n * 8))[0] = o0;
            ((float4*)(out + n * 8))[1] = o1;
        }
    }
}

// ---------------- launch ----------------
extern "C" void kernel_launch(void* const* d_in, const int* in_sizes, int n_in,
                              void* d_out, int out_size) {
    const float* x   = (const float*)d_in[0];
    const int*   src = (const int*)d_in[1];
    const int*   dst = (const int*)d_in[2];
    const float* W[5], *b[5], *al[5], *ar[5];
    for (int l = 0; l < 5; l++) {
        int i = 3 + 4 * l;
        W[l]  = (const float*)d_in[i];
        b[l]  = (const float*)d_in[i + 1];
        al[l] = (const float*)d_in[i + 2];
        ar[l] = (const float*)d_in[i + 3];
    }
    const float* Wo = (const float*)d_in[23];
    const float* bo = (const float*)d_in[24];
    float* out = (float*)d_out;

    const int NB_N = (NN + 255) / 256;
    const int NB_E = (NE + 255) / 256;
    const int NB_W = (NN * 32 + 255) / 256;   // warp-per-node kernels
    const int NB_G = (NN + 63) / 64;          // gemm: 64 rows/block (8 rows/warp)

    // gemm1 stays in the ncu capture slot (4th launch) to verify the L1->FMA pipe shift.
    zero_kernel<<<NB_N, 256>>>();
    count_kernel<<<NB_E, 256>>>(dst);
    scan_kernel<<<1, 1024>>>();
    gemm_kernel<128><<<NB_G, 256>>>(x, W[0], al[0], ar[0]);     // <- profiled slot
    fill_kernel<<<NB_E, 256>>>(src, dst);
    agg_kernel<false><<<NB_W, 256>>>(b[0], nullptr, nullptr, nullptr);

    for (int l = 1; l < 5; l++) {
        gemm_kernel<64><<<NB_G, 256>>>(nullptr, W[l], al[l], ar[l]);  // nullptr -> read g_h
        if (l < 4) agg_kernel<false><<<NB_W, 256>>>(b[l], nullptr, nullptr, nullptr);
        else       agg_kernel<true><<<NB_W, 256>>>(b[l], Wo, bo, out);  // fused final projection
    }
}

// round 17
// speedup vs baseline: 1.0614x; 1.0421x over previous
#include <cuda_runtime.h>
#include <cuda_fp16.h>

#define NN 50000
#define NE 800000
#define HID 64
#define HEADS 3
#define F3 192           // HEADS*HID
#define NCLS 8
#define FULLM 0xffffffffu

// ---------------- static device scratch (no allocations allowed) ----------------
__device__ __half g_feat[NN * F3];      // per-layer projected features, fp16 [N, 192] (19.2 MB, L2-resident)
__device__ float  g_h[NN * HID];        // per-layer node output (input to next layer), fp32
__device__ float4 g_el[NN];             // (el0, el1, el2, unused)
__device__ float4 g_er[NN];
__device__ int    g_deg[NN];
__device__ int    g_cur[NN];
__device__ int    g_off[NN + 1];
__device__ int    g_csr_src[NE];        // src node ids, grouped by dst

__device__ __forceinline__ float lrelu(float x, float s) { return x > 0.f ? x : x * s; }

// f32x2 packed FMA helpers (SASS FFMA2 — only reachable via PTX fma.rn.f32x2)
__device__ __forceinline__ unsigned long long dup2(float x) {
    unsigned long long r;
    unsigned u = __float_as_uint(x);
    asm("mov.b64 %0, {%1, %1};" : "=l"(r) : "r"(u));
    return r;
}
__device__ __forceinline__ void fma2(unsigned long long& d, unsigned long long a, unsigned long long b) {
    asm("fma.rn.f32x2 %0, %1, %2, %3;" : "=l"(d) : "l"(a), "l"(b), "l"(d));
}
__device__ __forceinline__ float f2lo(unsigned long long v) { return __uint_as_float((unsigned)(v & 0xffffffffULL)); }
__device__ __forceinline__ float f2hi(unsigned long long v) { return __uint_as_float((unsigned)(v >> 32)); }

// ---------------- CSR build ----------------
__global__ void zero_kernel() {
    int i = blockIdx.x * blockDim.x + threadIdx.x;
    if (i < NN) { g_deg[i] = 0; g_cur[i] = 0; }
}

__global__ void count_kernel(const int* __restrict__ dst) {
    int e = blockIdx.x * blockDim.x + threadIdx.x;
    if (e < NE) atomicAdd(&g_deg[dst[e]], 1);
}

__global__ void scan_kernel() {
    __shared__ int s[1024];
    int t = threadIdx.x;
    const int CH = (NN + 1023) / 1024;   // 49
    int lo = t * CH; if (lo > NN) lo = NN;
    int hi = lo + CH; if (hi > NN) hi = NN;
    int sum = 0;
    for (int i = lo; i < hi; i++) sum += g_deg[i];
    s[t] = sum;
    __syncthreads();
    for (int d = 1; d < 1024; d <<= 1) {
        int v = (t >= d) ? s[t - d] : 0;
        __syncthreads();
        s[t] += v;
        __syncthreads();
    }
    int run = (t == 0) ? 0 : s[t - 1];
    for (int i = lo; i < hi; i++) { g_off[i] = run; run += g_deg[i]; }
    if (t == 1023) g_off[NN] = s[1023];
}

__global__ void fill_kernel(const int* __restrict__ src, const int* __restrict__ dst) {
    int e = blockIdx.x * blockDim.x + threadIdx.x;
    if (e < NE) {
        int d = dst[e];
        int p = atomicAdd(&g_cur[d], 1);
        g_csr_src[g_off[d] + p] = src[e];
    }
}

// ---------------- projection GEMM + fused el/er: feat = h @ W  ([N,DIN] @ [DIN,192]) ----------------
// 512 threads (16 warps), each warp computes 8 rows x 192 cols (128 rows/block).
// R16 ncu: occ 23% (1x 8-warp block/SM) pinned issue at 49%. 16 warps/block restores 4
// warps/SMSP (regs 112*512=57K fits) while keeping the 8-rows/warp LDS amortization.
// Columns packed in pairs (c, c+96) into f32x2 accumulators -> FFMA2.
// Epilogue: el/er from fp32 accumulators; feat stored fp16. Per-row math bit-identical.
template <int DIN>
__global__ void __launch_bounds__(512) gemm_kernel(const float* __restrict__ hin,
                                                   const float* __restrict__ W,
                                                   const float* __restrict__ al,
                                                   const float* __restrict__ ar) {
    __shared__ float2 Ws[64 * 96];      // 48 KB
    const int lane = threadIdx.x & 31;
    const int warp = threadIdx.x >> 5;
    const int rowBase = blockIdx.x * 128 + warp * 8;
    const float* hp = hin ? hin : (const float*)g_h;
    const unsigned long long* Wsu = (const unsigned long long*)Ws;

    unsigned long long acc[8][3];
#pragma unroll
    for (int r = 0; r < 8; r++)
#pragma unroll
        for (int j = 0; j < 3; j++) acc[r][j] = 0ULL;

    for (int kt = 0; kt < DIN; kt += 64) {
        __syncthreads();
        // stage: 64 rows x 24 float4-pairs; Ws[k*96+c] = (W[k][c], W[k][c+96])
        for (int idx = threadIdx.x; idx < 64 * 24; idx += 512) {
            int k = idx / 24, cq = idx % 24;
            const float4* row = (const float4*)(W + (kt + k) * F3);
            float4 a = row[cq];
            float4 b = row[cq + 24];
            float2* d = &Ws[k * 96 + cq * 4];
            d[0] = make_float2(a.x, b.x);
            d[1] = make_float2(a.y, b.y);
            d[2] = make_float2(a.z, b.z);
            d[3] = make_float2(a.w, b.w);
        }
        __syncthreads();

        float h0[8], h1[8];
#pragma unroll
        for (int r = 0; r < 8; r++) {
            int row = rowBase + r;
            bool ok = row < NN;
            h0[r] = ok ? hp[row * DIN + kt + lane]      : 0.f;
            h1[r] = ok ? hp[row * DIN + kt + 32 + lane] : 0.f;
        }
#pragma unroll 4
        for (int kk = 0; kk < 32; kk++) {
            unsigned long long w0 = Wsu[kk * 96 + lane];
            unsigned long long w1 = Wsu[kk * 96 + lane + 32];
            unsigned long long w2 = Wsu[kk * 96 + lane + 64];
#pragma unroll
            for (int r = 0; r < 8; r++) {
                unsigned long long h2 = dup2(__shfl_sync(FULLM, h0[r], kk));
                fma2(acc[r][0], h2, w0);
                fma2(acc[r][1], h2, w1);
                fma2(acc[r][2], h2, w2);
            }
        }
#pragma unroll 4
        for (int kk = 0; kk < 32; kk++) {
            unsigned long long w0 = Wsu[(kk + 32) * 96 + lane];
            unsigned long long w1 = Wsu[(kk + 32) * 96 + lane + 32];
            unsigned long long w2 = Wsu[(kk + 32) * 96 + lane + 64];
#pragma unroll
            for (int r = 0; r < 8; r++) {
                unsigned long long h2 = dup2(__shfl_sync(FULLM, h1[r], kk));
                fma2(acc[r][0], h2, w0);
                fma2(acc[r][1], h2, w1);
                fma2(acc[r][2], h2, w2);
            }
        }
    }

    // al/ar constants for this lane's 6 columns: c = lane+32j (lo) and lane+96+32j (hi)
    float alc[6], arc[6];
#pragma unroll
    for (int j = 0; j < 3; j++) {
        alc[j]     = al[lane + 32 * j];
        alc[j + 3] = al[lane + 96 + 32 * j];
        arc[j]     = ar[lane + 32 * j];
        arc[j + 3] = ar[lane + 96 + 32 * j];
    }

#pragma unroll
    for (int r = 0; r < 8; r++) {
        int row = rowBase + r;
        if (row >= NN) continue;

        float lo0 = f2lo(acc[r][0]), lo1 = f2lo(acc[r][1]), lo2 = f2lo(acc[r][2]);
        float hi0 = f2hi(acc[r][0]), hi1 = f2hi(acc[r][1]), hi2 = f2hi(acc[r][2]);

        // store feat as fp16
        __half* fr = g_feat + row * F3;
        fr[lane]       = __float2half(lo0);
        fr[lane + 32]  = __float2half(lo1);
        fr[lane + 64]  = __float2half(lo2);
        fr[lane + 96]  = __float2half(hi0);
        fr[lane + 128] = __float2half(hi1);
        fr[lane + 160] = __float2half(hi2);

        // el/er per-lane partials (fp32, same grouping + reduction tree as before)
        float pl0 = fmaf(lo0, alc[0], lo1 * alc[1]);   // head0: cols lane, lane+32
        float pl1 = fmaf(lo2, alc[2], hi0 * alc[3]);   // head1: cols lane+64, lane+96
        float pl2 = fmaf(hi1, alc[4], hi2 * alc[5]);   // head2: cols lane+128, lane+160
        float pr0 = fmaf(lo0, arc[0], lo1 * arc[1]);
        float pr1 = fmaf(lo2, arc[2], hi0 * arc[3]);
        float pr2 = fmaf(hi1, arc[4], hi2 * arc[5]);
#pragma unroll
        for (int d = 16; d >= 1; d >>= 1) {
            pl0 += __shfl_xor_sync(FULLM, pl0, d);
            pl1 += __shfl_xor_sync(FULLM, pl1, d);
            pl2 += __shfl_xor_sync(FULLM, pl2, d);
            pr0 += __shfl_xor_sync(FULLM, pr0, d);
            pr1 += __shfl_xor_sync(FULLM, pr1, d);
            pr2 += __shfl_xor_sync(FULLM, pr2, d);
        }
        if (lane == 0) {
            g_el[row] = make_float4(pl0, pl1, pl2, 0.f);
            g_er[row] = make_float4(pr0, pr1, pr2, 0.f);
        }
    }
}

// ---------------- fused edge-softmax + aggregation + bias + LeakyReLU + head-mean ----------------
// One warp per destination node. SINGLE edge pass, no per-edge scratch (R14 structure).
// LAST=true additionally fuses the final projection out = h @ Wo + bo.
template <bool LAST>
__global__ void __launch_bounds__(256) agg_kernel(const float* __restrict__ b,
                                                  const float* __restrict__ Wo,
                                                  const float* __restrict__ bo,
                                                  float* __restrict__ out) {
    int gw = (blockIdx.x * blockDim.x + threadIdx.x) >> 5;
    int lane = threadIdx.x & 31;
    if (gw >= NN) return;
    const int n = gw;
    const int base = g_off[n];
    const int deg  = g_off[n + 1] - base;
    const float4 er4 = g_er[n];

    float sm0 = 0.f, sm1 = 0.f, sm2 = 0.f;
    float a1x = 0.f, a1y = 0.f, a1z = 0.f, a1w = 0.f;
    float a2x = 0.f, a2y = 0.f, a2z = 0.f, a2w = 0.f;

    for (int i0 = 0; i0 < deg; i0 += 32) {
        int rem = deg - i0;
        int cnt = rem < 32 ? rem : 32;
        bool v = lane < cnt;
        int sL = v ? g_csr_src[base + i0 + lane] : 0;              // coalesced, parallel
        float ex0L = 0.f, ex1L = 0.f, ex2L = 0.f;
        if (v) {
            float4 el4 = g_el[sL];                                 // lane-parallel gather
            ex0L = __expf(lrelu(el4.x + er4.x, 0.2f));
            ex1L = __expf(lrelu(el4.y + er4.y, 0.2f));
            ex2L = __expf(lrelu(el4.z + er4.z, 0.2f));
            sm0 += ex0L; sm1 += ex1L; sm2 += ex2L;
        }

        int j = 0;
        for (; j + 4 <= cnt; j += 4) {
            uint2 v1[4], v2[4];
            float ah[4], ez[4];
#pragma unroll
            for (int q = 0; q < 4; q++) {
                int   s   = __shfl_sync(FULLM, sL,   j + q);
                float ex0 = __shfl_sync(FULLM, ex0L, j + q);
                float ex1 = __shfl_sync(FULLM, ex1L, j + q);
                ez[q]     = __shfl_sync(FULLM, ex2L, j + q);
                ah[q] = (lane < 16) ? ex0 : ex1;
                const __half* fr = g_feat + s * F3;
                v1[q] = *(const uint2*)(fr + 4 * lane);
                if (lane < 16) v2[q] = *(const uint2*)(fr + 128 + 4 * lane);
            }
#pragma unroll
            for (int q = 0; q < 4; q++) {
                float2 p0 = __half22float2(*(const __half2*)&v1[q].x);
                float2 p1 = __half22float2(*(const __half2*)&v1[q].y);
                a1x = fmaf(ah[q], p0.x, a1x);
                a1y = fmaf(ah[q], p0.y, a1y);
                a1z = fmaf(ah[q], p1.x, a1z);
                a1w = fmaf(ah[q], p1.y, a1w);
                if (lane < 16) {
                    float2 q0 = __half22float2(*(const __half2*)&v2[q].x);
                    float2 q1 = __half22float2(*(const __half2*)&v2[q].y);
                    a2x = fmaf(ez[q], q0.x, a2x);
                    a2y = fmaf(ez[q], q0.y, a2y);
                    a2z = fmaf(ez[q], q1.x, a2z);
                    a2w = fmaf(ez[q], q1.y, a2w);
                }
            }
        }
        for (; j < cnt; j++) {
            int   s   = __shfl_sync(FULLM, sL,   j);
            float ex0 = __shfl_sync(FULLM, ex0L, j);
            float ex1 = __shfl_sync(FULLM, ex1L, j);
            float ex2 = __shfl_sync(FULLM, ex2L, j);
            float ah = (lane < 16) ? ex0 : ex1;
            const __half* fr = g_feat + s * F3;
            uint2 v1 = *(const uint2*)(fr + 4 * lane);
            float2 p0 = __half22float2(*(const __half2*)&v1.x);
            float2 p1 = __half22float2(*(const __half2*)&v1.y);
            a1x = fmaf(ah, p0.x, a1x);
            a1y = fmaf(ah, p0.y, a1y);
            a1z = fmaf(ah, p1.x, a1z);
            a1w = fmaf(ah, p1.y, a1w);
            if (lane < 16) {
                uint2 v2 = *(const uint2*)(fr + 128 + 4 * lane);
                float2 q0 = __half22float2(*(const __half2*)&v2.x);
                float2 q1 = __half22float2(*(const __half2*)&v2.y);
                a2x = fmaf(ex2, q0.x, a2x);
                a2y = fmaf(ex2, q0.y, a2y);
                a2z = fmaf(ex2, q1.x, a2z);
                a2w = fmaf(ex2, q1.y, a2w);
            }
        }
    }

    // reduce softmax sums across lanes
#pragma unroll
    for (int d = 16; d >= 1; d >>= 1) {
        sm0 += __shfl_xor_sync(FULLM, sm0, d);
        sm1 += __shfl_xor_sync(FULLM, sm1, d);
        sm2 += __shfl_xor_sync(FULLM, sm2, d);
    }
    float inv0 = sm0 > 0.f ? 1.f / sm0 : 0.f;
    float inv1 = sm1 > 0.f ? 1.f / sm1 : 0.f;
    float inv2 = sm2 > 0.f ? 1.f / sm2 : 0.f;

    // normalize (per-lane head inverse), then gather head-1 accumulators into lanes 0..15
    float invA = (lane < 16) ? inv0 : inv1;
    a1x *= invA; a1y *= invA; a1z *= invA; a1w *= invA;
    a2x *= inv2; a2y *= inv2; a2z *= inv2; a2w *= inv2;

    float h1x = __shfl_down_sync(FULLM, a1x, 16);
    float h1y = __shfl_down_sync(FULLM, a1y, 16);
    float h1z = __shfl_down_sync(FULLM, a1z, 16);
    float h1w = __shfl_down_sync(FULLM, a1w, 16);

    // lanes 0..15 compute o = h[4*lane .. 4*lane+3]
    float4 o = make_float4(0.f, 0.f, 0.f, 0.f);
    if (lane < 16) {
        const float4* bb = (const float4*)b;
        float4 B0 = bb[lane], B1 = bb[16 + lane], B2 = bb[32 + lane];
        const float third = 1.f / 3.f;
        o.x = (lrelu(a1x + B0.x, 0.01f) + lrelu(h1x + B1.x, 0.01f) + lrelu(a2x + B2.x, 0.01f)) * third;
        o.y = (lrelu(a1y + B0.y, 0.01f) + lrelu(h1y + B1.y, 0.01f) + lrelu(a2y + B2.y, 0.01f)) * third;
        o.z = (lrelu(a1z + B0.z, 0.01f) + lrelu(h1z + B1.z, 0.01f) + lrelu(a2z + B2.z, 0.01f)) * third;
        o.w = (lrelu(a1w + B0.w, 0.01f) + lrelu(h1w + B1.w, 0.01f) + lrelu(a2w + B2.w, 0.01f)) * third;
        if (!LAST) ((float4*)(g_h + n * HID))[lane] = o;
    }

    if (LAST) {
        // fused final projection: out[n] = h @ Wo + bo   (h held across lanes 0..15, 4 vals each)
        float p[8];
#pragma unroll
        for (int c = 0; c < 8; c++) p[c] = 0.f;
        if (lane < 16) {
            const float4* wr = (const float4*)(Wo + (4 * lane) * 8);  // rows 4l..4l+3, 2 float4 each
            float hv[4] = {o.x, o.y, o.z, o.w};
#pragma unroll
            for (int j = 0; j < 4; j++) {
                float4 wa = wr[2 * j];
                float4 wb = wr[2 * j + 1];
                p[0] = fmaf(hv[j], wa.x, p[0]);
                p[1] = fmaf(hv[j], wa.y, p[1]);
                p[2] = fmaf(hv[j], wa.z, p[2]);
                p[3] = fmaf(hv[j], wa.w, p[3]);
                p[4] = fmaf(hv[j], wb.x, p[4]);
                p[5] = fmaf(hv[j], wb.y, p[5]);
                p[6] = fmaf(hv[j], wb.z, p[6]);
                p[7] = fmaf(hv[j], wb.w, p[7]);
            }
        }
#pragma unroll
        for (int d = 8; d >= 1; d >>= 1) {
#pragma unroll
            for (int c = 0; c < 8; c++) p[c] += __shfl_xor_sync(FULLM, p[c], d);
        }
        if (lane == 0) {
            float4 o0 = make_float4(p[0] + bo[0], p[1] + bo[1], p[2] + bo[2], p[3] + bo[3]);
            float4 o1 = make_float4(p[4] + bo[4], p[5] + bo[5], p[6] + bo[6], p[7] + bo[7]);
            ((float4*)(out + n * 8))[0] = o0;
            ((float4*)(out + n * 8))[1] = o1;
        }
    }
}

// ---------------- launch ----------------
extern "C" void kernel_launch(void* const* d_in, const int* in_sizes, int n_in,
                              void* d_out, int out_size) {
    const float* x   = (const float*)d_in[0];
    const int*   src = (const int*)d_in[1];
    const int*   dst = (const int*)d_in[2];
    const float* W[5], *b[5], *al[5], *ar[5];
    for (int l = 0; l < 5; l++) {
        int i = 3 + 4 * l;
        W[l]  = (const float*)d_in[i];
        b[l]  = (const float*)d_in[i + 1];
        al[l] = (const float*)d_in[i + 2];
        ar[l] = (const float*)d_in[i + 3];
    }
    const float* Wo = (const float*)d_in[23];
    const float* bo = (const float*)d_in[24];
    float* out = (float*)d_out;

    const int NB_N = (NN + 255) / 256;
    const int NB_E = (NE + 255) / 256;
    const int NB_W = (NN * 32 + 255) / 256;   // warp-per-node kernels
    const int NB_G = (NN + 127) / 128;        // gemm: 128 rows/block (16 warps x 8 rows)

    // gemm1 stays in the ncu capture slot (4th launch) to verify occ/issue recovery.
    zero_kernel<<<NB_N, 256>>>();
    count_kernel<<<NB_E, 256>>>(dst);
    scan_kernel<<<1, 1024>>>();
    gemm_kernel<128><<<NB_G, 512>>>(x, W[0], al[0], ar[0]);     // <- profiled slot
    fill_kernel<<<NB_E, 256>>>(src, dst);
    agg_kernel<false><<<NB_W, 256>>>(b[0], nullptr, nullptr, nullptr);

    for (int l = 1; l < 5; l++) {
        gemm_kernel<64><<<NB_G, 512>>>(nullptr, W[l], al[l], ar[l]);  // nullptr -> read g_h
        if (l < 4) agg_kernel<false><<<NB_W, 256>>>(b[l], nullptr, nullptr, nullptr);
        else       agg_kernel<true><<<NB_W, 256>>>(b[l], Wo, bo, out);  // fused final projection
    }
}